// round 10
// baseline (speedup 1.0000x reference)
#include <cuda_runtime.h>

#define FULL 0xFFFFFFFFu

// Problem shape (fixed): N=1, L=S=512, H=8, D=M=32
constexpr int H = 8;
constexpr int NCH = 16;              // chunks per head (512/32)
constexpr int MATS = 3 * 1024 + 32;  // KK(1024) SQQ(1024) KV(1024) Ksum(32)
constexpr float K_SCALE = 0.05892556509887896f; // 1/(3*sqrt(32))

// Chunk-fastest partial layout: g_part[h][elem][chunk], 16 floats (64B) per
// element -> reduce of one element = 4 consecutive LDG.128.
__device__ __align__(16) float g_part[H * MATS * NCH];
__device__ __align__(16) float g_mats[H * MATS];
__device__ __align__(16) float g_Qn[512 * H * 32];
__device__ __align__(16) float g_Kn[512 * H * 32];
__device__ unsigned g_cnt[H * 64];   // per-head monotonic counters, 256B apart

__device__ __forceinline__ unsigned atom_add_acqrel(unsigned* p, unsigned v) {
    unsigned old;
    asm volatile("atom.acq_rel.gpu.add.u32 %0, [%1], %2;"
                 : "=r"(old) : "l"(p), "r"(v) : "memory");
    return old;
}

// ---------------------------------------------------------------------------
// K1: 128 CTAs (16 chunks x 8 heads), 32 rows each.
// LN + partial KK/SQQ/KV/Ksum (chunk-transposed) + last-CTA-per-head reduce.
// ---------------------------------------------------------------------------
__global__ __launch_bounds__(256) void k1_build(
        const float* __restrict__ q, const float* __restrict__ k,
        const float* __restrict__ v, const float* __restrict__ klen) {
    __shared__ __align__(16) float sQ[32][36];
    __shared__ __align__(16) float sK[32][36];
    __shared__ __align__(16) float sV[32][36];
    __shared__ int sIsLast;

    int bx = blockIdx.x;
    int h = bx & 7, c = bx >> 3;          // head, 32-row chunk
    int tid = threadIdx.x, lane = tid & 31, w = tid >> 5;

    // ---- load raw tiles: one float4 per thread per tensor ----
    int r4 = tid >> 3, c4 = (tid & 7) * 4;
    int g4 = ((c * 32 + r4) * H + h) * 32 + c4;
    *(float4*)&sQ[r4][c4] = *(const float4*)&q[g4];
    *(float4*)&sK[r4][c4] = *(const float4*)&k[g4];
    *(float4*)&sV[r4][c4] = *(const float4*)&v[g4];
    __syncthreads();

    // ---- LayerNorm: warp w -> rows w, w+8, w+16, w+24 ----
    #pragma unroll
    for (int rr = 0; rr < 4; rr++) {
        int r = w + rr * 8;
        float x = sQ[r][lane], y = sK[r][lane];
        float sx = x, sxx = x * x, sy = y, syy = y * y;
        #pragma unroll
        for (int o = 16; o; o >>= 1) {
            sx  += __shfl_xor_sync(FULL, sx,  o);
            sxx += __shfl_xor_sync(FULL, sxx, o);
            sy  += __shfl_xor_sync(FULL, sy,  o);
            syy += __shfl_xor_sync(FULL, syy, o);
        }
        float muq = sx * (1.0f / 32.0f);
        float vq  = fmaf(-muq, muq, sxx * (1.0f / 32.0f));
        sQ[r][lane] = (x - muq) * rsqrtf(vq + 1e-5f);
        float muk = sy * (1.0f / 32.0f);
        float vk  = fmaf(-muk, muk, syy * (1.0f / 32.0f));
        sK[r][lane] = (y - muk) * rsqrtf(vk + 1e-5f) * (K_SCALE * klen[c * 32 + r]);
    }
    __syncthreads();

    // ---- persist normalized Q/K for K2 ----
    *(float4*)&g_Qn[g4] = *(const float4*)&sQ[r4][c4];
    *(float4*)&g_Kn[g4] = *(const float4*)&sK[r4][c4];

    // ---- partial matrices (KK: w0-1, SQQ: w2-3, KV+Ksum: w4-7) ----
    // Element e of head h, chunk c -> g_part[(h*MATS + e)*NCH + c].
    float* outp = &g_part[((size_t)h * MATS) * NCH + c];
    if (tid < 128) {
        int t = tid & 63;
        const float (*X)[36] = (tid < 64) ? sK : sQ;
        int a0 = (t & 7) * 4, b0 = (t >> 3) * 4;
        float acc[4][4] = {};
        #pragma unroll 4
        for (int r = 0; r < 32; r++) {
            float4 xa = *(const float4*)&X[r][a0];
            float4 yb = *(const float4*)&X[r][b0];
            float xs[4] = {xa.x, xa.y, xa.z, xa.w};
            float ys[4] = {yb.x, yb.y, yb.z, yb.w};
            #pragma unroll
            for (int i = 0; i < 4; i++)
                #pragma unroll
                for (int j = 0; j < 4; j++)
                    acc[i][j] = fmaf(xs[i], ys[j], acc[i][j]);
        }
        int base = (tid < 64) ? 0 : 1024;
        #pragma unroll
        for (int i = 0; i < 4; i++)
            #pragma unroll
            for (int j = 0; j < 4; j++)
                outp[(size_t)(base + (a0 + i) * 32 + (b0 + j)) * NCH] = acc[i][j];
    } else {
        // KV[d][m] = sum_r K[r][d] V[r][m], 4x2 tile per thread
        int t = tid - 128;
        int a0 = (t & 7) * 4, b0 = (t >> 3) * 2;
        float acc[4][2] = {};
        #pragma unroll 4
        for (int r = 0; r < 32; r++) {
            float4 xa = *(const float4*)&sK[r][a0];
            float2 yb = *(const float2*)&sV[r][b0];
            float xs[4] = {xa.x, xa.y, xa.z, xa.w};
            #pragma unroll
            for (int i = 0; i < 4; i++) {
                acc[i][0] = fmaf(xs[i], yb.x, acc[i][0]);
                acc[i][1] = fmaf(xs[i], yb.y, acc[i][1]);
            }
        }
        #pragma unroll
        for (int i = 0; i < 4; i++) {
            outp[(size_t)(2048 + (a0 + i) * 32 + b0)     * NCH] = acc[i][0];
            outp[(size_t)(2048 + (a0 + i) * 32 + b0 + 1) * NCH] = acc[i][1];
        }
        if (t < 32) {
            float s = 0.0f;
            #pragma unroll
            for (int r = 0; r < 32; r++) s += sK[r][t];
            outp[(size_t)(3072 + t) * NCH] = s;
        }
    }

    // ---- last CTA of this head reduces its 16 partials (deterministic) ----
    __syncthreads();                      // all CTA stores before release
    if (tid == 0) {
        unsigned old = atom_add_acqrel(&g_cnt[h * 64], 1u);
        sIsLast = ((old & 15u) == 15u) ? 1 : 0;
    }
    __syncthreads();
    if (sIsLast) {
        const float4* pb = (const float4*)&g_part[((size_t)h * MATS) * NCH];
        for (int e = tid; e < MATS; e += 256) {
            const float4* p = pb + e * 4;       // 4 x float4 = 16 chunk values
            float4 a = __ldcg(p), b = __ldcg(p + 1);
            float4 c2 = __ldcg(p + 2), d2 = __ldcg(p + 3);
            float s = (((a.x + a.y) + (a.z + a.w)) + ((b.x + b.y) + (b.z + b.w)))
                    + (((c2.x + c2.y) + (c2.z + c2.w)) + ((d2.x + d2.y) + (d2.z + d2.w)));
            g_mats[h * MATS + e] = s;
        }
    }
}

// ---------------------------------------------------------------------------
// K2: 256 CTAs x 512 threads. One warp per output row.
// Flat unpadded smem matrices (row access only -> conflict-free).
// ---------------------------------------------------------------------------
__global__ __launch_bounds__(512) void k2_consume(
        const float* __restrict__ v, float* __restrict__ out) {
    __shared__ __align__(16) float sM[MATS];   // KK | SQQ | KV | Ksum

    int bx = blockIdx.x;
    int h = bx & 7, cb = bx >> 3;         // head, 16-row chunk
    int tid = threadIdx.x, lane = tid & 31, w = tid >> 5;

    // ---- stage this head's matrices: float4, 2 iters/thread ----
    {
        const float4* m4 = (const float4*)&g_mats[h * MATS];
        float4* s4 = (float4*)sM;
        #pragma unroll
        for (int i = tid; i < MATS / 4; i += 512) s4[i] = m4[i];
    }
    __syncthreads();

    // ---- epilogue: one row per warp ----
    int l = cb * 16 + w;
    int g = (l * H + h) * 32 + lane;
    float qv = g_Qn[g], kv = g_Kn[g], vv = v[g];

    float o1 = 0.0f, wq = 0.0f, wk = 0.0f;
    #pragma unroll
    for (int d = 0; d < 32; d++) {
        float qd = __shfl_sync(FULL, qv, d);
        float kd = __shfl_sync(FULL, kv, d);
        wq = fmaf(qd, sM[d * 32 + lane],        wq);   // KK row d
        wk = fmaf(kd, sM[1024 + d * 32 + lane], wk);   // SQQ row d
        o1 = fmaf(qd, sM[2048 + d * 32 + lane], o1);   // KV row d
    }
    float tn = fmaf(0.5f * wq, qv, qv * sM[3072 + lane]);  // norm partial
    float tc = wk * kv;                                     // k^T SQQ k partial
    #pragma unroll
    for (int o = 16; o; o >>= 1) {
        tn += __shfl_xor_sync(FULL, tn, o);
        tc += __shfl_xor_sync(FULL, tc, o);
    }
    out[g] = (o1 + 0.5f * tc * vv) / tn;
}

extern "C" void kernel_launch(void* const* d_in, const int* in_sizes, int n_in,
                              void* d_out, int out_size) {
    const float* q    = (const float*)d_in[0];
    const float* k    = (const float*)d_in[1];
    const float* v    = (const float*)d_in[2];
    // d_in[3] attn_mask, d_in[4] query_lengths: unused by the reference
    const float* klen = (const float*)d_in[5];
    float* out = (float*)d_out;

    k1_build<<<NCH * H, 256>>>(q, k, v, klen);     // 128 CTAs
    k2_consume<<<32 * H, 512>>>(v, out);           // 256 CTAs
}

// round 11
// speedup vs baseline: 1.6600x; 1.6600x over previous
#include <cuda_runtime.h>

#define FULL 0xFFFFFFFFu

// Problem shape (fixed): N=1, L=S=512, H=8, D=M=32
constexpr int H = 8;
constexpr int NCH = 16;              // 32-row chunks per head
constexpr int MATS = 3 * 1024 + 32;  // KK(1024) SQQ(1024) KV(1024) Ksum(32)
constexpr float K_SCALE = 0.05892556509887896f; // 1/(3*sqrt(32))

// Contiguous partial layout: g_part[cta][elem]  (cta = c*8 + h)
__device__ __align__(16) float g_part[NCH * H * MATS];
__device__ __align__(16) float g_mats[H * MATS];
__device__ __align__(16) float g_Qn[512 * H * 32];
__device__ __align__(16) float g_Kn[512 * H * 32];

// ---------------------------------------------------------------------------
// K1: 128 CTAs (16 chunks x 8 heads), 32 rows. LN + partial matrices,
// contiguous vector stores.
// ---------------------------------------------------------------------------
__global__ __launch_bounds__(256) void k1_build(
        const float* __restrict__ q, const float* __restrict__ k,
        const float* __restrict__ v, const float* __restrict__ klen) {
    __shared__ __align__(16) float sQ[32][36];
    __shared__ __align__(16) float sK[32][36];
    __shared__ __align__(16) float sV[32][36];

    int bx = blockIdx.x;
    int h = bx & 7, c = bx >> 3;
    int tid = threadIdx.x, lane = tid & 31, w = tid >> 5;

    // ---- load raw tiles: one float4 per thread per tensor ----
    int r4 = tid >> 3, c4 = (tid & 7) * 4;
    int g4 = ((c * 32 + r4) * H + h) * 32 + c4;
    *(float4*)&sQ[r4][c4] = *(const float4*)&q[g4];
    *(float4*)&sK[r4][c4] = *(const float4*)&k[g4];
    *(float4*)&sV[r4][c4] = *(const float4*)&v[g4];
    __syncthreads();

    // ---- LayerNorm: warp w -> rows w, w+8, w+16, w+24 ----
    #pragma unroll
    for (int rr = 0; rr < 4; rr++) {
        int r = w + rr * 8;
        float x = sQ[r][lane], y = sK[r][lane];
        float sx = x, sxx = x * x, sy = y, syy = y * y;
        #pragma unroll
        for (int o = 16; o; o >>= 1) {
            sx  += __shfl_xor_sync(FULL, sx,  o);
            sxx += __shfl_xor_sync(FULL, sxx, o);
            sy  += __shfl_xor_sync(FULL, sy,  o);
            syy += __shfl_xor_sync(FULL, syy, o);
        }
        float muq = sx * (1.0f / 32.0f);
        float vq  = fmaf(-muq, muq, sxx * (1.0f / 32.0f));
        sQ[r][lane] = (x - muq) * rsqrtf(vq + 1e-5f);
        float muk = sy * (1.0f / 32.0f);
        float vk  = fmaf(-muk, muk, syy * (1.0f / 32.0f));
        sK[r][lane] = (y - muk) * rsqrtf(vk + 1e-5f) * (K_SCALE * klen[c * 32 + r]);
    }
    __syncthreads();

    // ---- persist normalized Q/K for K3 ----
    *(float4*)&g_Qn[g4] = *(const float4*)&sQ[r4][c4];
    *(float4*)&g_Kn[g4] = *(const float4*)&sK[r4][c4];

    // ---- partial matrices (KK: w0-1, SQQ: w2-3, KV+Ksum: w4-7) ----
    float* outp = &g_part[(size_t)bx * MATS];
    if (tid < 128) {
        int t = tid & 63;
        const float (*X)[36] = (tid < 64) ? sK : sQ;
        int a0 = (t & 7) * 4, b0 = (t >> 3) * 4;
        float acc[4][4] = {};
        #pragma unroll 4
        for (int r = 0; r < 32; r++) {
            float4 xa = *(const float4*)&X[r][a0];
            float4 yb = *(const float4*)&X[r][b0];
            float xs[4] = {xa.x, xa.y, xa.z, xa.w};
            float ys[4] = {yb.x, yb.y, yb.z, yb.w};
            #pragma unroll
            for (int i = 0; i < 4; i++)
                #pragma unroll
                for (int j = 0; j < 4; j++)
                    acc[i][j] = fmaf(xs[i], ys[j], acc[i][j]);
        }
        int base = (tid < 64) ? 0 : 1024;
        #pragma unroll
        for (int i = 0; i < 4; i++)
            *(float4*)&outp[base + (a0 + i) * 32 + b0] =
                make_float4(acc[i][0], acc[i][1], acc[i][2], acc[i][3]);
    } else {
        int t = tid - 128;
        int a0 = (t & 7) * 4, b0 = (t >> 3) * 2;
        float acc[4][2] = {};
        #pragma unroll 4
        for (int r = 0; r < 32; r++) {
            float4 xa = *(const float4*)&sK[r][a0];
            float2 yb = *(const float2*)&sV[r][b0];
            float xs[4] = {xa.x, xa.y, xa.z, xa.w};
            #pragma unroll
            for (int i = 0; i < 4; i++) {
                acc[i][0] = fmaf(xs[i], yb.x, acc[i][0]);
                acc[i][1] = fmaf(xs[i], yb.y, acc[i][1]);
            }
        }
        #pragma unroll
        for (int i = 0; i < 4; i++)
            *(float2*)&outp[2048 + (a0 + i) * 32 + b0] =
                make_float2(acc[i][0], acc[i][1]);
        if (t < 32) {
            float s = 0.0f;
            #pragma unroll
            for (int r = 0; r < 32; r++) s += sK[r][t];
            outp[3072 + t] = s;
        }
    }
}

// ---------------------------------------------------------------------------
// K2: 32 CTAs (4 per head). Coalesced 16-way reduce into g_mats.
// Each warp load = 128B contiguous; 16-deep unrolled MLP.
// ---------------------------------------------------------------------------
__global__ __launch_bounds__(256) void k2_reduce() {
    int h = blockIdx.x & 7, p = blockIdx.x >> 3;   // head, quarter
    int tid = threadIdx.x;
    if (tid >= 194) return;
    int f4 = p * 194 + tid;                        // float4 index in [0,776)
    float4 s = make_float4(0.f, 0.f, 0.f, 0.f);
    #pragma unroll
    for (int cc = 0; cc < NCH; cc++) {
        const float4* pp = (const float4*)&g_part[((size_t)(cc * 8 + h)) * MATS];
        float4 a = pp[f4];
        s.x += a.x; s.y += a.y; s.z += a.z; s.w += a.w;
    }
    ((float4*)&g_mats[(size_t)h * MATS])[f4] = s;
}

// ---------------------------------------------------------------------------
// K3: 128 CTAs x 256 thr, 32 output rows each.
// GEMM-reformulated epilogue: T1 = Q*KK, T2 = K*SQQ, O1 = Q*KV as register-
// tile GEMMs, then cheap per-row dots.
// ---------------------------------------------------------------------------
__global__ __launch_bounds__(256) void k3_consume(
        const float* __restrict__ v, float* __restrict__ out) {
    __shared__ __align__(16) float sQt[32][36];  // transposed: sQt[d][l]
    __shared__ __align__(16) float sKt[32][36];  // transposed: sKt[d][l]
    __shared__ __align__(16) float sV [32][36];  // row-major
    __shared__ __align__(16) float sM [MATS];    // KK | SQQ | KV | Ksum
    __shared__ __align__(16) float sT1[32][36];  // (Q*KK)[l][e]
    __shared__ __align__(16) float sT2[32][36];  // (K*SQQ)[l][e]
    __shared__ __align__(16) float sO1[32][36];  // (Q*KV)[l][m]

    int bx = blockIdx.x;
    int h = bx & 7, c = bx >> 3;
    int tid = threadIdx.x, lane = tid & 31, w = tid >> 5;

    // ---- stage matrices (float4, coalesced) ----
    {
        const float4* m4 = (const float4*)&g_mats[(size_t)h * MATS];
        float4* s4 = (float4*)sM;
        #pragma unroll
        for (int i = tid; i < MATS / 4; i += 256) s4[i] = m4[i];
    }
    // ---- load Q/K (transpose via STS) and V (row-major) ----
    int r4 = tid >> 3, c4 = (tid & 7) * 4;
    int g4 = ((c * 32 + r4) * H + h) * 32 + c4;
    {
        float4 qv = *(const float4*)&g_Qn[g4];
        float4 kv = *(const float4*)&g_Kn[g4];
        *(float4*)&sV[r4][c4] = *(const float4*)&v[g4];
        sQt[c4 + 0][r4] = qv.x; sQt[c4 + 1][r4] = qv.y;
        sQt[c4 + 2][r4] = qv.z; sQt[c4 + 3][r4] = qv.w;
        sKt[c4 + 0][r4] = kv.x; sKt[c4 + 1][r4] = kv.y;
        sKt[c4 + 2][r4] = kv.z; sKt[c4 + 3][r4] = kv.w;
    }
    __syncthreads();

    // ---- 3 GEMMs: C[a][b] = sum_d X[d][a] * Y[d][b] ----
    if (tid < 128) {
        // T1 = Q*KK (thr 0-63), T2 = K*SQQ (thr 64-127): 4x4 tiles
        int t = tid & 63;
        const float (*X)[36] = (tid < 64) ? sQt : sKt;
        const float* Y = (tid < 64) ? &sM[0] : &sM[1024];
        float (*C)[36] = (tid < 64) ? sT1 : sT2;
        int a0 = (t & 7) * 4, b0 = (t >> 3) * 4;
        float acc[4][4] = {};
        #pragma unroll 4
        for (int d = 0; d < 32; d++) {
            float4 xa = *(const float4*)&X[d][a0];
            float4 yb = *(const float4*)&Y[d * 32 + b0];
            float xs[4] = {xa.x, xa.y, xa.z, xa.w};
            float ys[4] = {yb.x, yb.y, yb.z, yb.w};
            #pragma unroll
            for (int i = 0; i < 4; i++)
                #pragma unroll
                for (int j = 0; j < 4; j++)
                    acc[i][j] = fmaf(xs[i], ys[j], acc[i][j]);
        }
        #pragma unroll
        for (int i = 0; i < 4; i++)
            *(float4*)&C[a0 + i][b0] =
                make_float4(acc[i][0], acc[i][1], acc[i][2], acc[i][3]);
    } else {
        // O1 = Q*KV: 4x2 tiles (thr 128-255)
        int t = tid - 128;
        int a0 = (t & 7) * 4, b0 = (t >> 3) * 2;
        float acc[4][2] = {};
        #pragma unroll 4
        for (int d = 0; d < 32; d++) {
            float4 xa = *(const float4*)&sQt[d][a0];
            float2 yb = *(const float2*)&sM[2048 + d * 32 + b0];
            float xs[4] = {xa.x, xa.y, xa.z, xa.w};
            #pragma unroll
            for (int i = 0; i < 4; i++) {
                acc[i][0] = fmaf(xs[i], yb.x, acc[i][0]);
                acc[i][1] = fmaf(xs[i], yb.y, acc[i][1]);
            }
        }
        #pragma unroll
        for (int i = 0; i < 4; i++)
            *(float2*)&sO1[a0 + i][b0] = make_float2(acc[i][0], acc[i][1]);
    }
    __syncthreads();

    // ---- per-row finish: warp w -> rows 4w..4w+3 ----
    #pragma unroll
    for (int rr = 0; rr < 4; rr++) {
        int r = w * 4 + rr;
        float ql = sQt[lane][r];       // stride-36 column read
        float kl = sKt[lane][r];
        float tn = ql * fmaf(0.5f, sT1[r][lane], sM[3072 + lane]);
        float tc = 0.5f * kl * sT2[r][lane];
        #pragma unroll
        for (int o = 16; o; o >>= 1) {
            tn += __shfl_xor_sync(FULL, tn, o);
            tc += __shfl_xor_sync(FULL, tc, o);
        }
        int l = c * 32 + r;
        out[(l * H + h) * 32 + lane] =
            (sO1[r][lane] + tc * sV[r][lane]) / tn;
    }
}

extern "C" void kernel_launch(void* const* d_in, const int* in_sizes, int n_in,
                              void* d_out, int out_size) {
    const float* q    = (const float*)d_in[0];
    const float* k    = (const float*)d_in[1];
    const float* v    = (const float*)d_in[2];
    // d_in[3] attn_mask, d_in[4] query_lengths: unused by the reference
    const float* klen = (const float*)d_in[5];
    float* out = (float*)d_out;

    k1_build<<<NCH * H, 256>>>(q, k, v, klen);   // 128 CTAs
    k2_reduce<<<4 * H, 256>>>();                 // 32 CTAs
    k3_consume<<<NCH * H, 256>>>(v, out);        // 128 CTAs
}